// round 7
// baseline (speedup 1.0000x reference)
#include <cuda_runtime.h>
#include <cuda_bf16.h>
#include <math.h>
#include <float.h>
#include <stdint.h>

#define BATCH 2
#define NCTX  2048
#define DIM   512
#define HEADS 8
#define DHEAD 64
#define KNN   32
#define MDB   131072
#define MROWS (BATCH*NCTX)   // 4096
#define NCH   24             // logical K' = 1536 = 24 chunks of 64

// scratch (device globals; no allocation allowed)
__device__ float g_q[MROWS * DIM];
__device__ float g_o[MROWS * DIM];

__device__ __forceinline__ uint32_t smem_u32(const void* p) {
    uint32_t a;
    asm("{ .reg .u64 t; cvta.to.shared.u64 t, %1; cvt.u32.u64 %0, t; }" : "=r"(a) : "l"(p));
    return a;
}
#define SW128(x) ((x) ^ (((x) >> 3) & 0x70))

#define LDSM_X4(r0, r1, r2, r3, addr) \
    asm volatile("ldmatrix.sync.aligned.m8n8.x4.shared.b16 {%0,%1,%2,%3}, [%4];" \
        : "=r"(r0), "=r"(r1), "=r"(r2), "=r"(r3) : "r"(addr))

#define MMA16816(c, a, b0, b1) \
    asm volatile("mma.sync.aligned.m16n8k16.row.col.f32.bf16.bf16.f32 " \
        "{%0,%1,%2,%3}, {%4,%5,%6,%7}, {%8,%9}, {%0,%1,%2,%3};" \
        : "+f"((c)[0]), "+f"((c)[1]), "+f"((c)[2]), "+f"((c)[3]) \
        : "r"((a)[0]), "r"((a)[1]), "r"((a)[2]), "r"((a)[3]), "r"(b0), "r"(b1))

__device__ __forceinline__ uint32_t pack_hi(float a, float b) {
    __nv_bfloat162 v = __floats2bfloat162_rn(a, b);
    return *reinterpret_cast<uint32_t*>(&v);
}
__device__ __forceinline__ uint32_t pack_lo(float a, float b) {
    float la = a - __bfloat162float(__float2bfloat16(a));
    float lb = b - __bfloat162float(__float2bfloat16(b));
    __nv_bfloat162 v = __floats2bfloat162_rn(la, lb);
    return *reinterpret_cast<uint32_t*>(&v);
}

// ---------------------------------------------------------------------------
// Fused bf16x3 emulated-fp32 GEMM: C[M,N] = A[M,512] * B[N,512]^T, fp32 in/out.
// 24 logical K-chunks of 64: chunk c uses fp32 col block (c&7)*64;
// A-part = lo if c>=16 else hi; B-part = lo if (8<=c<16) else hi.
// CTA tile 128x128, 8 warps (2x4), warp 64x32, double-buffered SW128 smem.
// grid = (N/128, M/128), 256 threads.
// ---------------------------------------------------------------------------
#define TILEB (128 * 128)
#define SO_A0 0
#define SO_A1 TILEB
#define SO_B0 (2 * TILEB)
#define SO_B1 (3 * TILEB)
#define GSMEM (4 * TILEB)         // 64 KB

__global__ void __launch_bounds__(256, 1) gemm_fused(
    const float* __restrict__ A,
    const float* __restrict__ B,
    float* __restrict__ C, int N)
{
    extern __shared__ char smem[];
    uint32_t sb = smem_u32(smem);
    const int tid  = threadIdx.x;
    const int wid  = tid >> 5, lane = tid & 31;
    const int wr   = wid >> 2;
    const int wc   = wid & 3;
    const int row0 = blockIdx.y * 128, col0 = blockIdx.x * 128;

    // staging map: thread -> (row = tid>>1, half = tid&1 -> 32 fp32 cols)
    const int sr = tid >> 1;
    const int sh = tid & 1;
    const float* Abase = A + (long)(row0 + sr) * DIM + sh * 32;
    const float* Bbase = B + (long)(col0 + sr) * DIM + sh * 32;

    const uint32_t a_l = (uint32_t)((lane & 15) * 128 + ((lane >> 4) & 1) * 16);
    const uint32_t b_l = (uint32_t)(((lane & 7) + ((lane >> 4) & 1) * 8) * 128 + ((lane >> 3) & 1) * 16);
    const uint32_t aoff[2] = {SO_A0, SO_A1}, boff[2] = {SO_B0, SO_B1};

    float acc[4][4][4];
#pragma unroll
    for (int i = 0; i < 4; i++)
#pragma unroll
        for (int j = 0; j < 4; j++)
#pragma unroll
            for (int k = 0; k < 4; k++) acc[i][j][k] = 0.f;

    float4 fa[8], fb[8];

    // helper lambdas expanded manually: load chunk cc into fa/fb
#define LOAD_CHUNK(cc) do { \
        int k0 = ((cc) & 7) * 64; \
        _Pragma("unroll") \
        for (int i = 0; i < 8; i++) { \
            fa[i] = *(const float4*)(Abase + k0 + i * 4); \
            fb[i] = *(const float4*)(Bbase + k0 + i * 4); \
        } \
    } while (0)

    // convert fa/fb -> bf16 tiles in smem buffer bs for chunk cc
#define STORE_CHUNK(cc, bs) do { \
        bool alo = ((cc) >= 16); \
        bool blo = ((cc) >= 8) && ((cc) < 16); \
        _Pragma("unroll") \
        for (int p = 0; p < 4; p++) { \
            float4 x0 = fa[2 * p], x1 = fa[2 * p + 1]; \
            uint4 ua; \
            if (alo) ua = make_uint4(pack_lo(x0.x, x0.y), pack_lo(x0.z, x0.w), \
                                     pack_lo(x1.x, x1.y), pack_lo(x1.z, x1.w)); \
            else     ua = make_uint4(pack_hi(x0.x, x0.y), pack_hi(x0.z, x0.w), \
                                     pack_hi(x1.x, x1.y), pack_hi(x1.z, x1.w)); \
            *(uint4*)(smem + aoff[bs] + SW128(sr * 128 + sh * 64 + p * 16)) = ua; \
            float4 y0 = fb[2 * p], y1 = fb[2 * p + 1]; \
            uint4 ub; \
            if (blo) ub = make_uint4(pack_lo(y0.x, y0.y), pack_lo(y0.z, y0.w), \
                                     pack_lo(y1.x, y1.y), pack_lo(y1.z, y1.w)); \
            else     ub = make_uint4(pack_hi(y0.x, y0.y), pack_hi(y0.z, y0.w), \
                                     pack_hi(y1.x, y1.y), pack_hi(y1.z, y1.w)); \
            *(uint4*)(smem + boff[bs] + SW128(sr * 128 + sh * 64 + p * 16)) = ub; \
        } \
    } while (0)

    LOAD_CHUNK(0);
    STORE_CHUNK(0, 0);
    __syncthreads();

    for (int c = 0; c < NCH; c++) {
        int buf = c & 1;
        if (c + 1 < NCH) LOAD_CHUNK(c + 1);

        uint32_t sa  = sb + aoff[buf] + wr * (64 * 128);
        uint32_t sbm = sb + boff[buf] + wc * (32 * 128);

#pragma unroll
        for (int ks = 0; ks < 4; ks++) {
            uint32_t bf[8];
#pragma unroll
            for (int np = 0; np < 2; np++) {
                uint32_t x = b_l + np * 2048 + ks * 32;
                LDSM_X4(bf[np * 4 + 0], bf[np * 4 + 1], bf[np * 4 + 2], bf[np * 4 + 3],
                        sbm + SW128(x));
            }
#pragma unroll
            for (int mt = 0; mt < 4; mt++) {
                uint32_t af[4];
                uint32_t x = a_l + mt * 2048 + ks * 32;
                LDSM_X4(af[0], af[1], af[2], af[3], sa + SW128(x));
#pragma unroll
                for (int nt = 0; nt < 4; nt++)
                    MMA16816(acc[mt][nt], af, bf[nt * 2], bf[nt * 2 + 1]);
            }
        }

        if (c + 1 < NCH) {
            __syncthreads();                  // mma reads of next buf done (it was 2 chunks ago)
            STORE_CHUNK(c + 1, (c + 1) & 1);
        }
        __syncthreads();
    }

    const int qr = lane >> 2, qc = (lane & 3) * 2;
#pragma unroll
    for (int mt = 0; mt < 4; mt++) {
#pragma unroll
        for (int nt = 0; nt < 4; nt++) {
            int r = row0 + wr * 64 + mt * 16 + qr;
            int cc = col0 + wc * 32 + nt * 8 + qc;
            *(float2*)(C + (long)r * N + cc)       = make_float2(acc[mt][nt][0], acc[mt][nt][1]);
            *(float2*)(C + (long)(r + 8) * N + cc) = make_float2(acc[mt][nt][2], acc[mt][nt][3]);
        }
    }
}

// ---------------------------------------------------------------------------
// KNN attention (v1): one warp per query. Near the L1 wavefront floor.
// ---------------------------------------------------------------------------
__global__ void knn_attn(const float* __restrict__ mem_db,
                         const int*   __restrict__ knn_idx,
                         const int*   __restrict__ mem_mask,
                         const float* __restrict__ scale_param)
{
    const unsigned FULL = 0xffffffffu;
    int warp = (blockIdx.x * blockDim.x + threadIdx.x) >> 5;
    int lane = threadIdx.x & 31;
    if (warp >= BATCH * HEADS * NCTX) return;

    int n  = warp % NCTX;
    int bh = warp / NCTX;
    int h  = bh % HEADS;
    int b  = bh / HEADS;

    const float* qp = g_q + ((long)(b * NCTX + n) * DIM) + h * DHEAD;
    float q0 = qp[lane];
    float q1 = qp[lane + 32];

    float ss = q0 * q0 + q1 * q1;
#pragma unroll
    for (int o = 16; o > 0; o >>= 1) ss += __shfl_xor_sync(FULL, ss, o);
    float scale = expf(scale_param[h]);
    float inv = scale / fmaxf(sqrtf(ss), 1e-12f);
    q0 *= inv; q1 *= inv;

    long ib = (long)((b * HEADS + h) * NCTX + n) * KNN;
    int  idx = knn_idx[ib + lane];
    bool msk = mem_mask[ib + lane] != 0;

    const float* db = mem_db + (long)b * MDB * 2 * DHEAD;

    float sim = 0.f;
#pragma unroll
    for (int j = 0; j < KNN; j++) {
        int ij = __shfl_sync(FULL, idx, j);
        const float* kp = db + (long)ij * (2 * DHEAD);
        float p = fmaf(q0, kp[lane], q1 * kp[lane + 32]);
#pragma unroll
        for (int o = 16; o > 0; o >>= 1) p += __shfl_xor_sync(FULL, p, o);
        if (lane == j) sim = p;
    }

    sim = msk ? sim : -FLT_MAX;

    float m = sim;
#pragma unroll
    for (int o = 16; o > 0; o >>= 1) m = fmaxf(m, __shfl_xor_sync(FULL, m, o));
    float p = __expf(sim - m);
    float s = p;
#pragma unroll
    for (int o = 16; o > 0; o >>= 1) s += __shfl_xor_sync(FULL, s, o);
    float attn = p / s;

    float o0 = 0.f, o1 = 0.f;
#pragma unroll
    for (int j = 0; j < KNN; j++) {
        float a  = __shfl_sync(FULL, attn, j);
        int   ij = __shfl_sync(FULL, idx, j);
        const float* vp = db + (long)ij * (2 * DHEAD) + DHEAD;
        o0 = fmaf(a, vp[lane], o0);
        o1 = fmaf(a, vp[lane + 32], o1);
    }

    float* op = g_o + ((long)(b * NCTX + n) * DIM) + h * DHEAD;
    op[lane]      = o0;
    op[lane + 32] = o1;
}

// ---------------------------------------------------------------------------
extern "C" void kernel_launch(void* const* d_in, const int* in_sizes, int n_in,
                              void* d_out, int out_size)
{
    const float* x        = (const float*)d_in[0];
    const float* mem_db   = (const float*)d_in[1];
    const int*   knn_idx  = (const int*)d_in[2];
    const int*   mem_mask = (const int*)d_in[3];
    const float* Wq       = (const float*)d_in[4];
    // d_in[5] = Wkv : dead code in the reference, never used
    const float* Wout     = (const float*)d_in[6];
    const float* scale_p  = (const float*)d_in[7];
    float* out = (float*)d_out;

    float *qb, *ob;
    cudaGetSymbolAddress((void**)&qb, g_q);
    cudaGetSymbolAddress((void**)&ob, g_o);

    cudaFuncSetAttribute(gemm_fused, cudaFuncAttributeMaxDynamicSharedMemorySize, GSMEM);

    dim3 gGemm(DIM / 128, MROWS / 128);   // (4, 32) = 128 CTAs

    // 1) q = x @ Wq^T  (fused split + bf16x3 tensor-core GEMM)
    gemm_fused<<<gGemm, 256, GSMEM>>>(x, Wq, qb, DIM);

    // 2) gather-attention
    int nwarps = BATCH * HEADS * NCTX;            // 65536
    knn_attn<<<(nwarps * 32) / 256, 256>>>(mem_db, knn_idx, mem_mask, scale_p);

    // 3) out = attn_out @ Wout^T
    gemm_fused<<<gGemm, 256, GSMEM>>>(ob, Wout, out, DIM);
}

// round 8
// speedup vs baseline: 1.5080x; 1.5080x over previous
#include <cuda_runtime.h>
#include <cuda_bf16.h>
#include <math.h>
#include <float.h>
#include <stdint.h>

#define BATCH 2
#define NCTX  2048
#define DIM   512
#define HEADS 8
#define DHEAD 64
#define KNN   32
#define MDB   131072
#define MROWS (BATCH*NCTX)   // 4096
#define KS    1024           // bf16 storage: [hi(512) | lo(512)]
#define NCH   24             // logical K' = 1536 = 24 chunks of 64

// scratch (device globals; no allocation allowed)
__device__ float g_q[MROWS * DIM];
__device__ float g_o[MROWS * DIM];
__device__ __nv_bfloat16 g_a2[(size_t)MROWS * KS];  // 8 MB
__device__ __nv_bfloat16 g_b2[(size_t)DIM * KS];    // 1 MB

__device__ __forceinline__ uint32_t smem_u32(const void* p) {
    uint32_t a;
    asm("{ .reg .u64 t; cvta.to.shared.u64 t, %1; cvt.u32.u64 %0, t; }" : "=r"(a) : "l"(p));
    return a;
}
#define SW128(x) ((x) ^ (((x) >> 3) & 0x70))

#define LDSM_X4(r0, r1, r2, r3, addr) \
    asm volatile("ldmatrix.sync.aligned.m8n8.x4.shared.b16 {%0,%1,%2,%3}, [%4];" \
        : "=r"(r0), "=r"(r1), "=r"(r2), "=r"(r3) : "r"(addr))

#define MMA16816(c, a, b0, b1) \
    asm volatile("mma.sync.aligned.m16n8k16.row.col.f32.bf16.bf16.f32 " \
        "{%0,%1,%2,%3}, {%4,%5,%6,%7}, {%8,%9}, {%0,%1,%2,%3};" \
        : "+f"((c)[0]), "+f"((c)[1]), "+f"((c)[2]), "+f"((c)[3]) \
        : "r"((a)[0]), "r"((a)[1]), "r"((a)[2]), "r"((a)[3]), "r"(b0), "r"(b1))

// ---------------------------------------------------------------------------
// split: fp32 [rows, 512] -> bf16 [rows, 1024] = [hi | lo]
// ---------------------------------------------------------------------------
__global__ void split2(const float* __restrict__ in, __nv_bfloat16* __restrict__ out,
                       int rows)
{
    int idx = blockIdx.x * blockDim.x + threadIdx.x;
    if (idx >= rows * (DIM / 4)) return;
    int r  = idx / (DIM / 4);
    int c4 = (idx % (DIM / 4)) * 4;
    float4 v = *(const float4*)(in + (long)r * DIM + c4);

    float vv[4] = {v.x, v.y, v.z, v.w};
    unsigned long long hp = 0, lp = 0;
#pragma unroll
    for (int i = 0; i < 4; i++) {
        __nv_bfloat16 h = __float2bfloat16(vv[i]);
        __nv_bfloat16 l = __float2bfloat16(vv[i] - __bfloat162float(h));
        hp |= (unsigned long long)__bfloat16_as_ushort(h) << (16 * i);
        lp |= (unsigned long long)__bfloat16_as_ushort(l) << (16 * i);
    }
    __nv_bfloat16* base = out + (long)r * KS + c4;
    *(unsigned long long*)(base)       = hp;
    *(unsigned long long*)(base + 512) = lp;
}

// ---------------------------------------------------------------------------
// bf16 mma.sync GEMM (R5 version): C = A*B^T, emulated-fp32 3-term schedule.
// ---------------------------------------------------------------------------
#define TILEB (128 * 128)
#define SO_A0 0
#define SO_A1 TILEB
#define SO_B0 (2 * TILEB)
#define SO_B1 (3 * TILEB)
#define GSMEM (4 * TILEB)         // 64 KB

__device__ __forceinline__ int a_src(int c) { return (c < 8) ? c : c - 8; }
__device__ __forceinline__ int b_src(int c) { return (c < 16) ? c : c - 16; }

__global__ void __launch_bounds__(256, 1) gemm_mma(
    const __nv_bfloat16* __restrict__ A,
    const __nv_bfloat16* __restrict__ B,
    float* __restrict__ C, int N)
{
    extern __shared__ char smem[];
    uint32_t sb = smem_u32(smem);
    const int tid  = threadIdx.x;
    const int wid  = tid >> 5, lane = tid & 31;
    const int wr   = wid >> 2;
    const int wc   = wid & 3;
    const int row0 = blockIdx.y * 128, col0 = blockIdx.x * 128;

    const int sr = tid >> 3;
    const int sc = (tid & 7) * 16;

    const uint32_t a_l = (uint32_t)((lane & 15) * 128 + ((lane >> 4) & 1) * 16);
    const uint32_t b_l = (uint32_t)(((lane & 7) + ((lane >> 4) & 1) * 8) * 128 + ((lane >> 3) & 1) * 16);

    const uint32_t aoff[2] = {SO_A0, SO_A1}, boff[2] = {SO_B0, SO_B1};

    float acc[4][4][4];
#pragma unroll
    for (int i = 0; i < 4; i++)
#pragma unroll
        for (int j = 0; j < 4; j++)
#pragma unroll
            for (int k = 0; k < 4; k++) acc[i][j][k] = 0.f;

    uint4 va[4], vb[4];
#pragma unroll
    for (int i = 0; i < 4; i++) {
        int r = sr + i * 32;
        va[i] = *(const uint4*)(A + (long)(row0 + r) * KS + (sc >> 1));
        vb[i] = *(const uint4*)(B + (long)(col0 + r) * KS + (sc >> 1));
    }
#pragma unroll
    for (int i = 0; i < 4; i++) {
        int r = sr + i * 32;
        *(uint4*)(smem + SO_A0 + SW128(r * 128 + sc)) = va[i];
        *(uint4*)(smem + SO_B0 + SW128(r * 128 + sc)) = vb[i];
    }
    __syncthreads();

    for (int c = 0; c < NCH; c++) {
        int buf = c & 1;
        if (c + 1 < NCH) {
            int ka = a_src(c + 1) * 64, kb = b_src(c + 1) * 64;
#pragma unroll
            for (int i = 0; i < 4; i++) {
                int r = sr + i * 32;
                va[i] = *(const uint4*)(A + (long)(row0 + r) * KS + ka + (sc >> 1));
                vb[i] = *(const uint4*)(B + (long)(col0 + r) * KS + kb + (sc >> 1));
            }
        }

        uint32_t sa  = sb + aoff[buf] + wr * (64 * 128);
        uint32_t sbm = sb + boff[buf] + wc * (32 * 128);

#pragma unroll
        for (int ks = 0; ks < 4; ks++) {
            uint32_t bf[8];
#pragma unroll
            for (int np = 0; np < 2; np++) {
                uint32_t x = b_l + np * 2048 + ks * 32;
                LDSM_X4(bf[np * 4 + 0], bf[np * 4 + 1], bf[np * 4 + 2], bf[np * 4 + 3],
                        sbm + SW128(x));
            }
#pragma unroll
            for (int mt = 0; mt < 4; mt++) {
                uint32_t af[4];
                uint32_t x = a_l + mt * 2048 + ks * 32;
                LDSM_X4(af[0], af[1], af[2], af[3], sa + SW128(x));
#pragma unroll
                for (int nt = 0; nt < 4; nt++)
                    MMA16816(acc[mt][nt], af, bf[nt * 2], bf[nt * 2 + 1]);
            }
        }

        if (c + 1 < NCH) {
            int nb = (c + 1) & 1;
#pragma unroll
            for (int i = 0; i < 4; i++) {
                int r = sr + i * 32;
                *(uint4*)(smem + aoff[nb] + SW128(r * 128 + sc)) = va[i];
                *(uint4*)(smem + boff[nb] + SW128(r * 128 + sc)) = vb[i];
            }
        }
        __syncthreads();
    }

    const int qr = lane >> 2, qc = (lane & 3) * 2;
#pragma unroll
    for (int mt = 0; mt < 4; mt++) {
#pragma unroll
        for (int nt = 0; nt < 4; nt++) {
            int r = row0 + wr * 64 + mt * 16 + qr;
            int cc = col0 + wc * 32 + nt * 8 + qc;
            *(float2*)(C + (long)r * N + cc)       = make_float2(acc[mt][nt][0], acc[mt][nt][1]);
            *(float2*)(C + (long)(r + 8) * N + cc) = make_float2(acc[mt][nt][2], acc[mt][nt][3]);
        }
    }
}

// ---------------------------------------------------------------------------
// KNN attention v3: one warp per query; transpose-reduce (31 shfl) replaces
// the 192 reduction shuffles; idx/attn in tiny per-warp smem for the v phase.
// ---------------------------------------------------------------------------
__global__ void __launch_bounds__(256) knn_attn3(
    const float* __restrict__ mem_db,
    const int*   __restrict__ knn_idx,
    const int*   __restrict__ mem_mask,
    const float* __restrict__ scale_param)
{
    __shared__ int   s_idx[8][32];
    __shared__ float s_att[8][32];
    const unsigned FULL = 0xffffffffu;
    const int tid = threadIdx.x, lane = tid & 31, w = tid >> 5;

    const int warp = blockIdx.x * 8 + w;          // 0..32767
    const int n  = warp & (NCTX - 1);
    const int bh = warp >> 11;
    const int h  = bh & (HEADS - 1);
    const int b  = bh >> 3;

    // q load + normalize (5 shfl); scale folded in
    const float* qp = g_q + ((long)(b * NCTX + n) * DIM) + h * DHEAD;
    float q0 = qp[lane], q1 = qp[lane + 32];
    float ssum = q0 * q0 + q1 * q1;
#pragma unroll
    for (int o = 16; o > 0; o >>= 1) ssum += __shfl_xor_sync(FULL, ssum, o);
    float inv = expf(scale_param[h]) / fmaxf(sqrtf(ssum), 1e-12f);
    q0 *= inv; q1 *= inv;

    long ib = (long)((b * HEADS + h) * NCTX + n) * KNN;
    s_idx[w][lane] = knn_idx[ib + lane];
    int msk = mem_mask[ib + lane];
    __syncwarp();

    const float* db = mem_db + (long)b * MDB * 128;

    // per-lane partials for all 32 neighbors (coalesced row loads)
    float c[32];
#pragma unroll 8
    for (int j = 0; j < 32; j++) {
        long ij = s_idx[w][j];
        const float* kp = db + ij * 128;
        c[j] = fmaf(q0, kp[lane], q1 * kp[lane + 32]);
    }

    // butterfly transpose-reduce: lane ends with s_lane in c[0] (31 shfl)
#pragma unroll
    for (int half = 16; half >= 1; half >>= 1) {
        bool up = (lane & half) != 0;
#pragma unroll
        for (int i = 0; i < half; i++) {
            float mine = up ? c[i + half] : c[i];
            float oth  = up ? c[i] : c[i + half];
            c[i] = mine + __shfl_xor_sync(FULL, oth, half);
        }
    }
    float sim = msk ? c[0] : -FLT_MAX;

    // softmax over lanes (10 shfl)
    float m = sim;
#pragma unroll
    for (int o = 16; o > 0; o >>= 1) m = fmaxf(m, __shfl_xor_sync(FULL, m, o));
    float p = __expf(sim - m);
    float s = p;
#pragma unroll
    for (int o = 16; o > 0; o >>= 1) s += __shfl_xor_sync(FULL, s, o);
    s_att[w][lane] = p / s;
    __syncwarp();

    // v phase: attn/idx via LDS broadcast, zero shuffles
    float o0 = 0.f, o1 = 0.f;
#pragma unroll 8
    for (int j = 0; j < 32; j++) {
        long  ij = s_idx[w][j];
        float a  = s_att[w][j];
        const float* vp = db + ij * 128 + 64;
        o0 = fmaf(a, vp[lane], o0);
        o1 = fmaf(a, vp[lane + 32], o1);
    }

    float* op = g_o + ((long)(b * NCTX + n) * DIM) + h * DHEAD;
    op[lane]      = o0;
    op[lane + 32] = o1;
}

// ---------------------------------------------------------------------------
extern "C" void kernel_launch(void* const* d_in, const int* in_sizes, int n_in,
                              void* d_out, int out_size)
{
    const float* x        = (const float*)d_in[0];
    const float* mem_db   = (const float*)d_in[1];
    const int*   knn_idx  = (const int*)d_in[2];
    const int*   mem_mask = (const int*)d_in[3];
    const float* Wq       = (const float*)d_in[4];
    // d_in[5] = Wkv : dead code in the reference, never used
    const float* Wout     = (const float*)d_in[6];
    const float* scale_p  = (const float*)d_in[7];
    float* out = (float*)d_out;

    float *qb, *ob;
    __nv_bfloat16 *a2, *b2;
    cudaGetSymbolAddress((void**)&qb, g_q);
    cudaGetSymbolAddress((void**)&ob, g_o);
    cudaGetSymbolAddress((void**)&a2, g_a2);
    cudaGetSymbolAddress((void**)&b2, g_b2);

    cudaFuncSetAttribute(gemm_mma, cudaFuncAttributeMaxDynamicSharedMemorySize, GSMEM);

    dim3 gGemm(DIM / 128, MROWS / 128);   // (4, 32) = 128 CTAs
    const int splitA_blocks = (MROWS * (DIM / 4) + 255) / 256;  // 2048
    const int splitB_blocks = (DIM   * (DIM / 4) + 255) / 256;  // 256

    // 1) q = x @ Wq^T  (bf16x3 emulated-fp32 tensor-core GEMM)
    split2<<<splitA_blocks, 256>>>(x, a2, MROWS);
    split2<<<splitB_blocks, 256>>>(Wq, b2, DIM);
    gemm_mma<<<gGemm, 256, GSMEM>>>(a2, b2, qb, DIM);

    // 2) gather-attention (transpose-reduce, low-shuffle)
    int nwarps = BATCH * HEADS * NCTX;            // 32768
    knn_attn3<<<nwarps / 8, 256>>>(mem_db, knn_idx, mem_mask, scale_p);

    // 3) out = attn_out @ Wout^T
    split2<<<splitA_blocks, 256>>>(ob, a2, MROWS);
    split2<<<splitB_blocks, 256>>>(Wout, b2, DIM);
    gemm_mma<<<gGemm, 256, GSMEM>>>(a2, b2, out, DIM);
}

// round 9
// speedup vs baseline: 1.8858x; 1.2506x over previous
#include <cuda_runtime.h>
#include <cuda_bf16.h>
#include <math.h>
#include <float.h>
#include <stdint.h>

#define BATCH 2
#define NCTX  2048
#define DIM   512
#define HEADS 8
#define DHEAD 64
#define KNN   32
#define MDB   131072
#define MROWS (BATCH*NCTX)   // 4096
#define KS    1024           // bf16 storage: [hi(512) | lo(512)]
#define NCH   24             // logical K' = 1536 = 24 chunks of 64

// scratch (device globals; no allocation allowed)
__device__ float g_q[MROWS * DIM];
__device__ float g_o[MROWS * DIM];
__device__ __nv_bfloat16 g_a2[(size_t)MROWS * KS];   // 8 MB
__device__ __nv_bfloat16 g_b2q[(size_t)DIM * KS];    // 1 MB
__device__ __nv_bfloat16 g_b2o[(size_t)DIM * KS];    // 1 MB

__device__ __forceinline__ uint32_t smem_u32(const void* p) {
    uint32_t a;
    asm("{ .reg .u64 t; cvta.to.shared.u64 t, %1; cvt.u32.u64 %0, t; }" : "=r"(a) : "l"(p));
    return a;
}
#define SW128(x) ((x) ^ (((x) >> 3) & 0x70))

#define LDSM_X4(r0, r1, r2, r3, addr) \
    asm volatile("ldmatrix.sync.aligned.m8n8.x4.shared.b16 {%0,%1,%2,%3}, [%4];" \
        : "=r"(r0), "=r"(r1), "=r"(r2), "=r"(r3) : "r"(addr))

#define MMA16816(c, a, b0, b1) \
    asm volatile("mma.sync.aligned.m16n8k16.row.col.f32.bf16.bf16.f32 " \
        "{%0,%1,%2,%3}, {%4,%5,%6,%7}, {%8,%9}, {%0,%1,%2,%3};" \
        : "+f"((c)[0]), "+f"((c)[1]), "+f"((c)[2]), "+f"((c)[3]) \
        : "r"((a)[0]), "r"((a)[1]), "r"((a)[2]), "r"((a)[3]), "r"(b0), "r"(b1))

// ---------------------------------------------------------------------------
// split helper: one fp32 row-slice -> bf16 [hi|lo] row
// ---------------------------------------------------------------------------
__device__ __forceinline__ void split_row4(const float* __restrict__ src,
                                           __nv_bfloat16* __restrict__ dst)
{
    float4 v = *(const float4*)src;
    float vv[4] = {v.x, v.y, v.z, v.w};
    unsigned long long hp = 0, lp = 0;
#pragma unroll
    for (int i = 0; i < 4; i++) {
        __nv_bfloat16 h = __float2bfloat16(vv[i]);
        __nv_bfloat16 l = __float2bfloat16(vv[i] - __bfloat162float(h));
        hp |= (unsigned long long)__bfloat16_as_ushort(h) << (16 * i);
        lp |= (unsigned long long)__bfloat16_as_ushort(l) << (16 * i);
    }
    *(unsigned long long*)(dst)       = hp;
    *(unsigned long long*)(dst + 512) = lp;
}

// split all inputs in one launch: x (4096 rows), Wq (512), Wout (512)
__global__ void split_all(const float* __restrict__ x,
                          const float* __restrict__ Wq,
                          const float* __restrict__ Wout)
{
    int idx = blockIdx.x * blockDim.x + threadIdx.x;   // over 5120*(512/4)
    int r  = idx / (DIM / 4);
    int c4 = (idx % (DIM / 4)) * 4;
    if (r < MROWS) {
        split_row4(x + (long)r * DIM + c4, g_a2 + (long)r * KS + c4);
    } else if (r < MROWS + DIM) {
        int rr = r - MROWS;
        split_row4(Wq + (long)rr * DIM + c4, g_b2q + (long)rr * KS + c4);
    } else {
        int rr = r - MROWS - DIM;
        split_row4(Wout + (long)rr * DIM + c4, g_b2o + (long)rr * KS + c4);
    }
}

// split attention output
__global__ void split_o()
{
    int idx = blockIdx.x * blockDim.x + threadIdx.x;
    int r  = idx / (DIM / 4);
    int c4 = (idx % (DIM / 4)) * 4;
    split_row4(g_o + (long)r * DIM + c4, g_a2 + (long)r * KS + c4);
}

// ---------------------------------------------------------------------------
// bf16 mma.sync GEMM (R5 version): C = A*B^T, emulated-fp32 3-term schedule.
// ---------------------------------------------------------------------------
#define TILEB (128 * 128)
#define SO_A0 0
#define SO_A1 TILEB
#define SO_B0 (2 * TILEB)
#define SO_B1 (3 * TILEB)
#define GSMEM (4 * TILEB)         // 64 KB

__device__ __forceinline__ int a_src(int c) { return (c < 8) ? c : c - 8; }
__device__ __forceinline__ int b_src(int c) { return (c < 16) ? c : c - 16; }

__global__ void __launch_bounds__(256, 1) gemm_mma(
    const __nv_bfloat16* __restrict__ A,
    const __nv_bfloat16* __restrict__ B,
    float* __restrict__ C, int N)
{
    extern __shared__ char smem[];
    uint32_t sb = smem_u32(smem);
    const int tid  = threadIdx.x;
    const int wid  = tid >> 5, lane = tid & 31;
    const int wr   = wid >> 2;
    const int wc   = wid & 3;
    const int row0 = blockIdx.y * 128, col0 = blockIdx.x * 128;

    const int sr = tid >> 3;
    const int sc = (tid & 7) * 16;

    const uint32_t a_l = (uint32_t)((lane & 15) * 128 + ((lane >> 4) & 1) * 16);
    const uint32_t b_l = (uint32_t)(((lane & 7) + ((lane >> 4) & 1) * 8) * 128 + ((lane >> 3) & 1) * 16);

    const uint32_t aoff[2] = {SO_A0, SO_A1}, boff[2] = {SO_B0, SO_B1};

    float acc[4][4][4];
#pragma unroll
    for (int i = 0; i < 4; i++)
#pragma unroll
        for (int j = 0; j < 4; j++)
#pragma unroll
            for (int k = 0; k < 4; k++) acc[i][j][k] = 0.f;

    uint4 va[4], vb[4];
#pragma unroll
    for (int i = 0; i < 4; i++) {
        int r = sr + i * 32;
        va[i] = *(const uint4*)(A + (long)(row0 + r) * KS + (sc >> 1));
        vb[i] = *(const uint4*)(B + (long)(col0 + r) * KS + (sc >> 1));
    }
#pragma unroll
    for (int i = 0; i < 4; i++) {
        int r = sr + i * 32;
        *(uint4*)(smem + SO_A0 + SW128(r * 128 + sc)) = va[i];
        *(uint4*)(smem + SO_B0 + SW128(r * 128 + sc)) = vb[i];
    }
    __syncthreads();

    for (int c = 0; c < NCH; c++) {
        int buf = c & 1;
        if (c + 1 < NCH) {
            int ka = a_src(c + 1) * 64, kb = b_src(c + 1) * 64;
#pragma unroll
            for (int i = 0; i < 4; i++) {
                int r = sr + i * 32;
                va[i] = *(const uint4*)(A + (long)(row0 + r) * KS + ka + (sc >> 1));
                vb[i] = *(const uint4*)(B + (long)(col0 + r) * KS + kb + (sc >> 1));
            }
        }

        uint32_t sa  = sb + aoff[buf] + wr * (64 * 128);
        uint32_t sbm = sb + boff[buf] + wc * (32 * 128);

#pragma unroll
        for (int ks = 0; ks < 4; ks++) {
            uint32_t bf[8];
#pragma unroll
            for (int np = 0; np < 2; np++) {
                uint32_t x = b_l + np * 2048 + ks * 32;
                LDSM_X4(bf[np * 4 + 0], bf[np * 4 + 1], bf[np * 4 + 2], bf[np * 4 + 3],
                        sbm + SW128(x));
            }
#pragma unroll
            for (int mt = 0; mt < 4; mt++) {
                uint32_t af[4];
                uint32_t x = a_l + mt * 2048 + ks * 32;
                LDSM_X4(af[0], af[1], af[2], af[3], sa + SW128(x));
#pragma unroll
                for (int nt = 0; nt < 4; nt++)
                    MMA16816(acc[mt][nt], af, bf[nt * 2], bf[nt * 2 + 1]);
            }
        }

        if (c + 1 < NCH) {
            int nb = (c + 1) & 1;
#pragma unroll
            for (int i = 0; i < 4; i++) {
                int r = sr + i * 32;
                *(uint4*)(smem + aoff[nb] + SW128(r * 128 + sc)) = va[i];
                *(uint4*)(smem + boff[nb] + SW128(r * 128 + sc)) = vb[i];
            }
        }
        __syncthreads();
    }

    const int qr = lane >> 2, qc = (lane & 3) * 2;
#pragma unroll
    for (int mt = 0; mt < 4; mt++) {
#pragma unroll
        for (int nt = 0; nt < 4; nt++) {
            int r = row0 + wr * 64 + mt * 16 + qr;
            int cc = col0 + wc * 32 + nt * 8 + qc;
            *(float2*)(C + (long)r * N + cc)       = make_float2(acc[mt][nt][0], acc[mt][nt][1]);
            *(float2*)(C + (long)(r + 8) * N + cc) = make_float2(acc[mt][nt][2], acc[mt][nt][3]);
        }
    }
}

// ---------------------------------------------------------------------------
// KNN attention v4: one warp per query; two neighbors per iteration on
// 16-lane halves, float4 gathers, 4-shfl pair reduce. ~83 shfl/warp.
// ---------------------------------------------------------------------------
__global__ void __launch_bounds__(256) knn_attn4(
    const float* __restrict__ mem_db,
    const int*   __restrict__ knn_idx,
    const int*   __restrict__ mem_mask,
    const float* __restrict__ scale_param)
{
    __shared__ int   s_idx[8][32];
    __shared__ float s_q[8][64];
    __shared__ float s_sim[8][32];
    __shared__ float s_att[8][32];
    const unsigned FULL = 0xffffffffu;
    const int tid = threadIdx.x, lane = tid & 31, w = tid >> 5;

    const int warp = blockIdx.x * 8 + w;          // 0..32767
    const int n  = warp & (NCTX - 1);
    const int bh = warp >> 11;
    const int h  = bh & (HEADS - 1);
    const int b  = bh >> 3;

    // q load + normalize (5 shfl); scale folded in; stage to smem
    const float* qp = g_q + ((long)(b * NCTX + n) * DIM) + h * DHEAD;
    float q0 = qp[lane], q1 = qp[lane + 32];
    float ssum = q0 * q0 + q1 * q1;
#pragma unroll
    for (int o = 16; o > 0; o >>= 1) ssum += __shfl_xor_sync(FULL, ssum, o);
    float inv = expf(scale_param[h]) / fmaxf(sqrtf(ssum), 1e-12f);
    s_q[w][lane]      = q0 * inv;
    s_q[w][lane + 32] = q1 * inv;

    long ib = (long)((b * HEADS + h) * NCTX + n) * KNN;
    s_idx[w][lane] = knn_idx[ib + lane];
    int msk = mem_mask[ib + lane];
    __syncwarp();

    const float* db = mem_db + (long)b * MDB * 128;
    const int hl = lane >> 4;          // half id: neighbor parity
    const int sl = lane & 15;          // float4 slot within row

    float4 q4 = *(const float4*)&s_q[w][sl * 4];

    // k phase: iteration i covers neighbors 2i (lanes 0-15) and 2i+1 (16-31)
#pragma unroll 4
    for (int i = 0; i < 16; i++) {
        int  nb = 2 * i + hl;
        long ij = s_idx[w][nb];
        float4 k4 = *(const float4*)(db + ij * 128 + sl * 4);
        float p = fmaf(q4.x, k4.x, fmaf(q4.y, k4.y, fmaf(q4.z, k4.z, q4.w * k4.w)));
        p += __shfl_xor_sync(FULL, p, 8);
        p += __shfl_xor_sync(FULL, p, 4);
        p += __shfl_xor_sync(FULL, p, 2);
        p += __shfl_xor_sync(FULL, p, 1);
        if (sl == 0) s_sim[w][nb] = p;         // lanes 0 and 16 write
    }
    __syncwarp();

    float sim = msk ? s_sim[w][lane] : -FLT_MAX;

    // softmax over lanes (10 shfl)
    float m = sim;
#pragma unroll
    for (int o = 16; o > 0; o >>= 1) m = fmaxf(m, __shfl_xor_sync(FULL, m, o));
    float p = __expf(sim - m);
    float s = p;
#pragma unroll
    for (int o = 16; o > 0; o >>= 1) s += __shfl_xor_sync(FULL, s, o);
    s_att[w][lane] = p / s;
    __syncwarp();

    // v phase: zero-shuffle accumulate; halves handle even/odd neighbors
    float4 acc = make_float4(0.f, 0.f, 0.f, 0.f);
#pragma unroll 4
    for (int i = 0; i < 16; i++) {
        int  nb = 2 * i + hl;
        long ij = s_idx[w][nb];
        float a = s_att[w][nb];
        float4 v4 = *(const float4*)(db + ij * 128 + 64 + sl * 4);
        acc.x = fmaf(a, v4.x, acc.x);
        acc.y = fmaf(a, v4.y, acc.y);
        acc.z = fmaf(a, v4.z, acc.z);
        acc.w = fmaf(a, v4.w, acc.w);
    }
    // combine halves (4 shfl)
    acc.x += __shfl_xor_sync(FULL, acc.x, 16);
    acc.y += __shfl_xor_sync(FULL, acc.y, 16);
    acc.z += __shfl_xor_sync(FULL, acc.z, 16);
    acc.w += __shfl_xor_sync(FULL, acc.w, 16);

    if (lane < 16) {
        float* op = g_o + ((long)(b * NCTX + n) * DIM) + h * DHEAD;
        *(float4*)(op + sl * 4) = acc;
    }
}

// ---------------------------------------------------------------------------
extern "C" void kernel_launch(void* const* d_in, const int* in_sizes, int n_in,
                              void* d_out, int out_size)
{
    const float* x        = (const float*)d_in[0];
    const float* mem_db   = (const float*)d_in[1];
    const int*   knn_idx  = (const int*)d_in[2];
    const int*   mem_mask = (const int*)d_in[3];
    const float* Wq       = (const float*)d_in[4];
    // d_in[5] = Wkv : dead code in the reference, never used
    const float* Wout     = (const float*)d_in[6];
    const float* scale_p  = (const float*)d_in[7];
    float* out = (float*)d_out;

    float *qb;
    __nv_bfloat16 *a2, *b2q, *b2o;
    cudaGetSymbolAddress((void**)&qb,  g_q);
    cudaGetSymbolAddress((void**)&a2,  g_a2);
    cudaGetSymbolAddress((void**)&b2q, g_b2q);
    cudaGetSymbolAddress((void**)&b2o, g_b2o);

    cudaFuncSetAttribute(gemm_mma, cudaFuncAttributeMaxDynamicSharedMemorySize, GSMEM);

    dim3 gGemm(DIM / 128, MROWS / 128);   // (4, 32) = 128 CTAs

    // 1) split x, Wq, Wout in one launch; then q = x @ Wq^T
    split_all<<<((MROWS + 2 * DIM) * (DIM / 4)) / 256, 256>>>(x, Wq, Wout);
    gemm_mma<<<gGemm, 256, GSMEM>>>(a2, b2q, qb, DIM);

    // 2) gather-attention (paired-neighbor low-shuffle)
    int nwarps = BATCH * HEADS * NCTX;            // 32768
    knn_attn4<<<nwarps / 8, 256>>>(mem_db, knn_idx, mem_mask, scale_p);

    // 3) split attention output; out = attn_out @ Wout^T
    split_o<<<(MROWS * (DIM / 4)) / 256, 256>>>();
    gemm_mma<<<gGemm, 256, GSMEM>>>(a2, b2o, out, DIM);
}

// round 10
// speedup vs baseline: 1.9509x; 1.0345x over previous
#include <cuda_runtime.h>
#include <cuda_bf16.h>
#include <math.h>
#include <float.h>
#include <stdint.h>

#define BATCH 2
#define NCTX  2048
#define DIM   512
#define HEADS 8
#define DHEAD 64
#define KNN   32
#define MDB   131072
#define MROWS (BATCH*NCTX)   // 4096
#define KS    1024           // bf16 storage: [hi(512) | lo(512)]
#define NCH   24             // logical K' = 1536 = 24 chunks of 64

// scratch (device globals; no allocation allowed)
__device__ float g_q[MROWS * DIM];
__device__ __nv_bfloat16 g_a2[(size_t)MROWS * KS];   // 8 MB
__device__ __nv_bfloat16 g_b2q[(size_t)DIM * KS];    // 1 MB
__device__ __nv_bfloat16 g_b2o[(size_t)DIM * KS];    // 1 MB

__device__ __forceinline__ uint32_t smem_u32(const void* p) {
    uint32_t a;
    asm("{ .reg .u64 t; cvta.to.shared.u64 t, %1; cvt.u32.u64 %0, t; }" : "=r"(a) : "l"(p));
    return a;
}
#define SW128(x) ((x) ^ (((x) >> 3) & 0x70))

#define LDSM_X4(r0, r1, r2, r3, addr) \
    asm volatile("ldmatrix.sync.aligned.m8n8.x4.shared.b16 {%0,%1,%2,%3}, [%4];" \
        : "=r"(r0), "=r"(r1), "=r"(r2), "=r"(r3) : "r"(addr))

#define MMA16816(c, a, b0, b1) \
    asm volatile("mma.sync.aligned.m16n8k16.row.col.f32.bf16.bf16.f32 " \
        "{%0,%1,%2,%3}, {%4,%5,%6,%7}, {%8,%9}, {%0,%1,%2,%3};" \
        : "+f"((c)[0]), "+f"((c)[1]), "+f"((c)[2]), "+f"((c)[3]) \
        : "r"((a)[0]), "r"((a)[1]), "r"((a)[2]), "r"((a)[3]), "r"(b0), "r"(b1))

// ---------------------------------------------------------------------------
// split helper: 4 fp32 -> packed bf16 hi (ull) and lo (ull)
// ---------------------------------------------------------------------------
__device__ __forceinline__ void split_pack4(const float* vv,
                                            unsigned long long& hp,
                                            unsigned long long& lp)
{
    hp = 0; lp = 0;
#pragma unroll
    for (int i = 0; i < 4; i++) {
        __nv_bfloat16 h = __float2bfloat16(vv[i]);
        __nv_bfloat16 l = __float2bfloat16(vv[i] - __bfloat162float(h));
        hp |= (unsigned long long)__bfloat16_as_ushort(h) << (16 * i);
        lp |= (unsigned long long)__bfloat16_as_ushort(l) << (16 * i);
    }
}

__device__ __forceinline__ void split_row4(const float* __restrict__ src,
                                           __nv_bfloat16* __restrict__ dst)
{
    float4 v = *(const float4*)src;
    float vv[4] = {v.x, v.y, v.z, v.w};
    unsigned long long hp, lp;
    split_pack4(vv, hp, lp);
    *(unsigned long long*)(dst)       = hp;
    *(unsigned long long*)(dst + 512) = lp;
}

// split all inputs in one launch: x (4096 rows), Wq (512), Wout (512)
__global__ void split_all(const float* __restrict__ x,
                          const float* __restrict__ Wq,
                          const float* __restrict__ Wout)
{
    int idx = blockIdx.x * blockDim.x + threadIdx.x;   // over 5120*(512/4)
    int r  = idx / (DIM / 4);
    int c4 = (idx % (DIM / 4)) * 4;
    if (r < MROWS) {
        split_row4(x + (long)r * DIM + c4, g_a2 + (long)r * KS + c4);
    } else if (r < MROWS + DIM) {
        int rr = r - MROWS;
        split_row4(Wq + (long)rr * DIM + c4, g_b2q + (long)rr * KS + c4);
    } else {
        int rr = r - MROWS - DIM;
        split_row4(Wout + (long)rr * DIM + c4, g_b2o + (long)rr * KS + c4);
    }
}

// ---------------------------------------------------------------------------
// bf16 mma.sync GEMM (R5 version): C = A*B^T, emulated-fp32 3-term schedule.
// ---------------------------------------------------------------------------
#define TILEB (128 * 128)
#define SO_A0 0
#define SO_A1 TILEB
#define SO_B0 (2 * TILEB)
#define SO_B1 (3 * TILEB)
#define GSMEM (4 * TILEB)         // 64 KB

__device__ __forceinline__ int a_src(int c) { return (c < 8) ? c : c - 8; }
__device__ __forceinline__ int b_src(int c) { return (c < 16) ? c : c - 16; }

__global__ void __launch_bounds__(256, 1) gemm_mma(
    const __nv_bfloat16* __restrict__ A,
    const __nv_bfloat16* __restrict__ B,
    float* __restrict__ C, int N)
{
    extern __shared__ char smem[];
    uint32_t sb = smem_u32(smem);
    const int tid  = threadIdx.x;
    const int wid  = tid >> 5, lane = tid & 31;
    const int wr   = wid >> 2;
    const int wc   = wid & 3;
    const int row0 = blockIdx.y * 128, col0 = blockIdx.x * 128;

    const int sr = tid >> 3;
    const int sc = (tid & 7) * 16;

    const uint32_t a_l = (uint32_t)((lane & 15) * 128 + ((lane >> 4) & 1) * 16);
    const uint32_t b_l = (uint32_t)(((lane & 7) + ((lane >> 4) & 1) * 8) * 128 + ((lane >> 3) & 1) * 16);

    const uint32_t aoff[2] = {SO_A0, SO_A1}, boff[2] = {SO_B0, SO_B1};

    float acc[4][4][4];
#pragma unroll
    for (int i = 0; i < 4; i++)
#pragma unroll
        for (int j = 0; j < 4; j++)
#pragma unroll
            for (int k = 0; k < 4; k++) acc[i][j][k] = 0.f;

    uint4 va[4], vb[4];
#pragma unroll
    for (int i = 0; i < 4; i++) {
        int r = sr + i * 32;
        va[i] = *(const uint4*)(A + (long)(row0 + r) * KS + (sc >> 1));
        vb[i] = *(const uint4*)(B + (long)(col0 + r) * KS + (sc >> 1));
    }
#pragma unroll
    for (int i = 0; i < 4; i++) {
        int r = sr + i * 32;
        *(uint4*)(smem + SO_A0 + SW128(r * 128 + sc)) = va[i];
        *(uint4*)(smem + SO_B0 + SW128(r * 128 + sc)) = vb[i];
    }
    __syncthreads();

    for (int c = 0; c < NCH; c++) {
        int buf = c & 1;
        if (c + 1 < NCH) {
            int ka = a_src(c + 1) * 64, kb = b_src(c + 1) * 64;
#pragma unroll
            for (int i = 0; i < 4; i++) {
                int r = sr + i * 32;
                va[i] = *(const uint4*)(A + (long)(row0 + r) * KS + ka + (sc >> 1));
                vb[i] = *(const uint4*)(B + (long)(col0 + r) * KS + kb + (sc >> 1));
            }
        }

        uint32_t sa  = sb + aoff[buf] + wr * (64 * 128);
        uint32_t sbm = sb + boff[buf] + wc * (32 * 128);

#pragma unroll
        for (int ks = 0; ks < 4; ks++) {
            uint32_t bf[8];
#pragma unroll
            for (int np = 0; np < 2; np++) {
                uint32_t x = b_l + np * 2048 + ks * 32;
                LDSM_X4(bf[np * 4 + 0], bf[np * 4 + 1], bf[np * 4 + 2], bf[np * 4 + 3],
                        sbm + SW128(x));
            }
#pragma unroll
            for (int mt = 0; mt < 4; mt++) {
                uint32_t af[4];
                uint32_t x = a_l + mt * 2048 + ks * 32;
                LDSM_X4(af[0], af[1], af[2], af[3], sa + SW128(x));
#pragma unroll
                for (int nt = 0; nt < 4; nt++)
                    MMA16816(acc[mt][nt], af, bf[nt * 2], bf[nt * 2 + 1]);
            }
        }

        if (c + 1 < NCH) {
            int nb = (c + 1) & 1;
#pragma unroll
            for (int i = 0; i < 4; i++) {
                int r = sr + i * 32;
                *(uint4*)(smem + aoff[nb] + SW128(r * 128 + sc)) = va[i];
                *(uint4*)(smem + boff[nb] + SW128(r * 128 + sc)) = vb[i];
            }
        }
        __syncthreads();
    }

    const int qr = lane >> 2, qc = (lane & 3) * 2;
#pragma unroll
    for (int mt = 0; mt < 4; mt++) {
#pragma unroll
        for (int nt = 0; nt < 4; nt++) {
            int r = row0 + wr * 64 + mt * 16 + qr;
            int cc = col0 + wc * 32 + nt * 8 + qc;
            *(float2*)(C + (long)r * N + cc)       = make_float2(acc[mt][nt][0], acc[mt][nt][1]);
            *(float2*)(C + (long)(r + 8) * N + cc) = make_float2(acc[mt][nt][2], acc[mt][nt][3]);
        }
    }
}

// ---------------------------------------------------------------------------
// KNN attention v5: v4 core + fused bf16 hi/lo epilogue straight into g_a2.
// ---------------------------------------------------------------------------
__global__ void __launch_bounds__(256) knn_attn5(
    const float* __restrict__ mem_db,
    const int*   __restrict__ knn_idx,
    const int*   __restrict__ mem_mask,
    const float* __restrict__ scale_param)
{
    __shared__ int   s_idx[8][32];
    __shared__ float s_q[8][64];
    __shared__ float s_sim[8][32];
    __shared__ float s_att[8][32];
    const unsigned FULL = 0xffffffffu;
    const int tid = threadIdx.x, lane = tid & 31, w = tid >> 5;

    const int warp = blockIdx.x * 8 + w;          // 0..32767
    const int n  = warp & (NCTX - 1);
    const int bh = warp >> 11;
    const int h  = bh & (HEADS - 1);
    const int b  = bh >> 3;

    // q load + normalize (5 shfl); scale folded in; stage to smem
    const float* qp = g_q + ((long)(b * NCTX + n) * DIM) + h * DHEAD;
    float q0 = qp[lane], q1 = qp[lane + 32];
    float ssum = q0 * q0 + q1 * q1;
#pragma unroll
    for (int o = 16; o > 0; o >>= 1) ssum += __shfl_xor_sync(FULL, ssum, o);
    float inv = expf(scale_param[h]) / fmaxf(sqrtf(ssum), 1e-12f);
    s_q[w][lane]      = q0 * inv;
    s_q[w][lane + 32] = q1 * inv;

    long ib = (long)((b * HEADS + h) * NCTX + n) * KNN;
    s_idx[w][lane] = knn_idx[ib + lane];
    int msk = mem_mask[ib + lane];
    __syncwarp();

    const float* db = mem_db + (long)b * MDB * 128;
    const int hl = lane >> 4;          // half id: neighbor parity
    const int sl = lane & 15;          // float4 slot within row

    float4 q4 = *(const float4*)&s_q[w][sl * 4];

    // k phase: iteration i covers neighbors 2i (lanes 0-15) and 2i+1 (16-31)
#pragma unroll 4
    for (int i = 0; i < 16; i++) {
        int  nb = 2 * i + hl;
        long ij = s_idx[w][nb];
        float4 k4 = *(const float4*)(db + ij * 128 + sl * 4);
        float p = fmaf(q4.x, k4.x, fmaf(q4.y, k4.y, fmaf(q4.z, k4.z, q4.w * k4.w)));
        p += __shfl_xor_sync(FULL, p, 8);
        p += __shfl_xor_sync(FULL, p, 4);
        p += __shfl_xor_sync(FULL, p, 2);
        p += __shfl_xor_sync(FULL, p, 1);
        if (sl == 0) s_sim[w][nb] = p;         // lanes 0 and 16 write
    }
    __syncwarp();

    float sim = msk ? s_sim[w][lane] : -FLT_MAX;

    // softmax over lanes (10 shfl)
    float m = sim;
#pragma unroll
    for (int o = 16; o > 0; o >>= 1) m = fmaxf(m, __shfl_xor_sync(FULL, m, o));
    float p = __expf(sim - m);
    float s = p;
#pragma unroll
    for (int o = 16; o > 0; o >>= 1) s += __shfl_xor_sync(FULL, s, o);
    s_att[w][lane] = p / s;
    __syncwarp();

    // v phase: zero-shuffle accumulate; halves handle even/odd neighbors
    float4 acc = make_float4(0.f, 0.f, 0.f, 0.f);
#pragma unroll 4
    for (int i = 0; i < 16; i++) {
        int  nb = 2 * i + hl;
        long ij = s_idx[w][nb];
        float a = s_att[w][nb];
        float4 v4 = *(const float4*)(db + ij * 128 + 64 + sl * 4);
        acc.x = fmaf(a, v4.x, acc.x);
        acc.y = fmaf(a, v4.y, acc.y);
        acc.z = fmaf(a, v4.z, acc.z);
        acc.w = fmaf(a, v4.w, acc.w);
    }
    // combine halves (4 shfl)
    acc.x += __shfl_xor_sync(FULL, acc.x, 16);
    acc.y += __shfl_xor_sync(FULL, acc.y, 16);
    acc.z += __shfl_xor_sync(FULL, acc.z, 16);
    acc.w += __shfl_xor_sync(FULL, acc.w, 16);

    if (lane < 16) {
        // fused epilogue: write bf16 hi/lo split directly into g_a2
        float vv[4] = {acc.x, acc.y, acc.z, acc.w};
        unsigned long long hp, lp;
        split_pack4(vv, hp, lp);
        __nv_bfloat16* dst = g_a2 + (long)(b * NCTX + n) * KS + h * DHEAD + sl * 4;
        *(unsigned long long*)(dst)       = hp;
        *(unsigned long long*)(dst + 512) = lp;
    }
}

// ---------------------------------------------------------------------------
extern "C" void kernel_launch(void* const* d_in, const int* in_sizes, int n_in,
                              void* d_out, int out_size)
{
    const float* x        = (const float*)d_in[0];
    const float* mem_db   = (const float*)d_in[1];
    const int*   knn_idx  = (const int*)d_in[2];
    const int*   mem_mask = (const int*)d_in[3];
    const float* Wq       = (const float*)d_in[4];
    // d_in[5] = Wkv : dead code in the reference, never used
    const float* Wout     = (const float*)d_in[6];
    const float* scale_p  = (const float*)d_in[7];
    float* out = (float*)d_out;

    float *qb;
    __nv_bfloat16 *a2, *b2q, *b2o;
    cudaGetSymbolAddress((void**)&qb,  g_q);
    cudaGetSymbolAddress((void**)&a2,  g_a2);
    cudaGetSymbolAddress((void**)&b2q, g_b2q);
    cudaGetSymbolAddress((void**)&b2o, g_b2o);

    cudaFuncSetAttribute(gemm_mma, cudaFuncAttributeMaxDynamicSharedMemorySize, GSMEM);

    dim3 gGemm(DIM / 128, MROWS / 128);   // (4, 32) = 128 CTAs

    // 1) split x, Wq, Wout in one launch; then q = x @ Wq^T
    split_all<<<((MROWS + 2 * DIM) * (DIM / 4)) / 256, 256>>>(x, Wq, Wout);
    gemm_mma<<<gGemm, 256, GSMEM>>>(a2, b2q, qb, DIM);

    // 2) gather-attention; epilogue writes bf16 split directly into g_a2
    int nwarps = BATCH * HEADS * NCTX;            // 32768
    knn_attn5<<<nwarps / 8, 256>>>(mem_db, knn_idx, mem_mask, scale_p);

    // 3) out = attn_out @ Wout^T
    gemm_mma<<<gGemm, 256, GSMEM>>>(a2, b2o, out, DIM);
}

// round 11
// speedup vs baseline: 2.0003x; 1.0253x over previous
#include <cuda_runtime.h>
#include <cuda_bf16.h>
#include <math.h>
#include <float.h>
#include <stdint.h>

#define BATCH 2
#define NCTX  2048
#define DIM   512
#define HEADS 8
#define DHEAD 64
#define KNN   32
#define MDB   131072
#define MROWS (BATCH*NCTX)   // 4096
#define KS    1024           // bf16 storage: [hi(512) | lo(512)]
#define NCH   24             // logical K' = 1536 = 24 chunks of 64

// scratch (device globals; no allocation allowed)
__device__ float g_q[MROWS * DIM];
__device__ __nv_bfloat16 g_a2[(size_t)MROWS * KS];   // 8 MB
__device__ __nv_bfloat16 g_b2q[(size_t)DIM * KS];    // 1 MB
__device__ __nv_bfloat16 g_b2o[(size_t)DIM * KS];    // 1 MB

__device__ __forceinline__ uint32_t smem_u32(const void* p) {
    uint32_t a;
    asm("{ .reg .u64 t; cvta.to.shared.u64 t, %1; cvt.u32.u64 %0, t; }" : "=r"(a) : "l"(p));
    return a;
}
#define SW128(x) ((x) ^ (((x) >> 3) & 0x70))

#define LDSM_X4(r0, r1, r2, r3, addr) \
    asm volatile("ldmatrix.sync.aligned.m8n8.x4.shared.b16 {%0,%1,%2,%3}, [%4];" \
        : "=r"(r0), "=r"(r1), "=r"(r2), "=r"(r3) : "r"(addr))

#define MMA16816(c, a, b0, b1) \
    asm volatile("mma.sync.aligned.m16n8k16.row.col.f32.bf16.bf16.f32 " \
        "{%0,%1,%2,%3}, {%4,%5,%6,%7}, {%8,%9}, {%0,%1,%2,%3};" \
        : "+f"((c)[0]), "+f"((c)[1]), "+f"((c)[2]), "+f"((c)[3]) \
        : "r"((a)[0]), "r"((a)[1]), "r"((a)[2]), "r"((a)[3]), "r"(b0), "r"(b1))

#define CP_ASYNC16(dst, src) \
    asm volatile("cp.async.cg.shared.global [%0], [%1], 16;" :: "r"(dst), "l"(src))
#define CP_COMMIT() asm volatile("cp.async.commit_group;" ::: "memory")
#define CP_WAIT1()  asm volatile("cp.async.wait_group 1;" ::: "memory")

// ---------------------------------------------------------------------------
// split helper: 4 fp32 -> packed bf16 hi (ull) and lo (ull)
// ---------------------------------------------------------------------------
__device__ __forceinline__ void split_pack4(const float* vv,
                                            unsigned long long& hp,
                                            unsigned long long& lp)
{
    hp = 0; lp = 0;
#pragma unroll
    for (int i = 0; i < 4; i++) {
        __nv_bfloat16 h = __float2bfloat16(vv[i]);
        __nv_bfloat16 l = __float2bfloat16(vv[i] - __bfloat162float(h));
        hp |= (unsigned long long)__bfloat16_as_ushort(h) << (16 * i);
        lp |= (unsigned long long)__bfloat16_as_ushort(l) << (16 * i);
    }
}

__device__ __forceinline__ void split_row4(const float* __restrict__ src,
                                           __nv_bfloat16* __restrict__ dst)
{
    float4 v = *(const float4*)src;
    float vv[4] = {v.x, v.y, v.z, v.w};
    unsigned long long hp, lp;
    split_pack4(vv, hp, lp);
    *(unsigned long long*)(dst)       = hp;
    *(unsigned long long*)(dst + 512) = lp;
}

// split all inputs in one launch: x (4096 rows), Wq (512), Wout (512)
__global__ void split_all(const float* __restrict__ x,
                          const float* __restrict__ Wq,
                          const float* __restrict__ Wout)
{
    int idx = blockIdx.x * blockDim.x + threadIdx.x;   // over 5120*(512/4)
    int r  = idx / (DIM / 4);
    int c4 = (idx % (DIM / 4)) * 4;
    if (r < MROWS) {
        split_row4(x + (long)r * DIM + c4, g_a2 + (long)r * KS + c4);
    } else if (r < MROWS + DIM) {
        int rr = r - MROWS;
        split_row4(Wq + (long)rr * DIM + c4, g_b2q + (long)rr * KS + c4);
    } else {
        int rr = r - MROWS - DIM;
        split_row4(Wout + (long)rr * DIM + c4, g_b2o + (long)rr * KS + c4);
    }
}

// ---------------------------------------------------------------------------
// bf16 mma.sync GEMM with cp.async 3-stage pipeline.
// C = A*B^T, emulated-fp32 3-term schedule (K'=1536 over [hi|lo] storage).
// CTA tile 128x128, 8 warps (2x4), warp 64x32, BK=64.
// ---------------------------------------------------------------------------
#define STILE  (128 * 128)        // 16 KB per operand per stage
#define SA_OFF(s) ((s) * STILE)
#define SB_OFF(s) (3 * STILE + (s) * STILE)
#define GSMEM  (6 * STILE)        // 96 KB

__device__ __forceinline__ int a_src(int c) { return (c < 8) ? c : c - 8; }
__device__ __forceinline__ int b_src(int c) { return (c < 16) ? c : c - 16; }

__global__ void __launch_bounds__(256, 1) gemm_mma(
    const __nv_bfloat16* __restrict__ A,
    const __nv_bfloat16* __restrict__ B,
    float* __restrict__ C, int N)
{
    extern __shared__ char smem[];
    uint32_t sb = smem_u32(smem);
    const int tid  = threadIdx.x;
    const int wid  = tid >> 5, lane = tid & 31;
    const int wr   = wid >> 2;
    const int wc   = wid & 3;
    const int row0 = blockIdx.y * 128, col0 = blockIdx.x * 128;

    const int sr = tid >> 3;            // 0..31
    const int sc = (tid & 7) * 16;      // byte col in 128B row

    const uint32_t a_l = (uint32_t)((lane & 15) * 128 + ((lane >> 4) & 1) * 16);
    const uint32_t b_l = (uint32_t)(((lane & 7) + ((lane >> 4) & 1) * 8) * 128 + ((lane >> 3) & 1) * 16);

    float acc[4][4][4];
#pragma unroll
    for (int i = 0; i < 4; i++)
#pragma unroll
        for (int j = 0; j < 4; j++)
#pragma unroll
            for (int k = 0; k < 4; k++) acc[i][j][k] = 0.f;

    // issue chunk cc's copies into stage s (8 x 16B per thread), one group
#define ISSUE(cc, s) do { \
        int ka = a_src(cc) * 64, kb = b_src(cc) * 64; \
        _Pragma("unroll") \
        for (int i = 0; i < 4; i++) { \
            int r = sr + i * 32; \
            uint32_t da = sb + SA_OFF(s) + SW128(r * 128 + sc); \
            CP_ASYNC16(da, A + (long)(row0 + r) * KS + ka + (sc >> 1)); \
            uint32_t dbm = sb + SB_OFF(s) + SW128(r * 128 + sc); \
            CP_ASYNC16(dbm, B + (long)(col0 + r) * KS + kb + (sc >> 1)); \
        } \
        CP_COMMIT(); \
    } while (0)

    ISSUE(0, 0);
    ISSUE(1, 1);

    for (int c = 0; c < NCH; c++) {
        int s = c % 3;
        CP_WAIT1();                    // stage c's group complete
        __syncthreads();

        uint32_t sa  = sb + SA_OFF(s) + wr * (64 * 128);
        uint32_t sbm = sb + SB_OFF(s) + wc * (32 * 128);

#pragma unroll
        for (int ks = 0; ks < 4; ks++) {
            uint32_t bf[8];
#pragma unroll
            for (int np = 0; np < 2; np++) {
                uint32_t x = b_l + np * 2048 + ks * 32;
                LDSM_X4(bf[np * 4 + 0], bf[np * 4 + 1], bf[np * 4 + 2], bf[np * 4 + 3],
                        sbm + SW128(x));
            }
#pragma unroll
            for (int mt = 0; mt < 4; mt++) {
                uint32_t af[4];
                uint32_t x = a_l + mt * 2048 + ks * 32;
                LDSM_X4(af[0], af[1], af[2], af[3], sa + SW128(x));
#pragma unroll
                for (int nt = 0; nt < 4; nt++)
                    MMA16816(acc[mt][nt], af, bf[nt * 2], bf[nt * 2 + 1]);
            }
        }
        __syncthreads();               // all warps done reading stage s

        if (c + 2 < NCH) ISSUE(c + 2, (c + 2) % 3);
    }

    const int qr = lane >> 2, qc = (lane & 3) * 2;
#pragma unroll
    for (int mt = 0; mt < 4; mt++) {
#pragma unroll
        for (int nt = 0; nt < 4; nt++) {
            int r = row0 + wr * 64 + mt * 16 + qr;
            int cc = col0 + wc * 32 + nt * 8 + qc;
            *(float2*)(C + (long)r * N + cc)       = make_float2(acc[mt][nt][0], acc[mt][nt][1]);
            *(float2*)(C + (long)(r + 8) * N + cc) = make_float2(acc[mt][nt][2], acc[mt][nt][3]);
        }
    }
#undef ISSUE
}

// ---------------------------------------------------------------------------
// KNN attention v5: paired-neighbor low-shuffle core + fused bf16 epilogue.
// ---------------------------------------------------------------------------
__global__ void __launch_bounds__(256) knn_attn5(
    const float* __restrict__ mem_db,
    const int*   __restrict__ knn_idx,
    const int*   __restrict__ mem_mask,
    const float* __restrict__ scale_param)
{
    __shared__ int   s_idx[8][32];
    __shared__ float s_q[8][64];
    __shared__ float s_sim[8][32];
    __shared__ float s_att[8][32];
    const unsigned FULL = 0xffffffffu;
    const int tid = threadIdx.x, lane = tid & 31, w = tid >> 5;

    const int warp = blockIdx.x * 8 + w;          // 0..32767
    const int n  = warp & (NCTX - 1);
    const int bh = warp >> 11;
    const int h  = bh & (HEADS - 1);
    const int b  = bh >> 3;

    const float* qp = g_q + ((long)(b * NCTX + n) * DIM) + h * DHEAD;
    float q0 = qp[lane], q1 = qp[lane + 32];
    float ssum = q0 * q0 + q1 * q1;
#pragma unroll
    for (int o = 16; o > 0; o >>= 1) ssum += __shfl_xor_sync(FULL, ssum, o);
    float inv = expf(scale_param[h]) / fmaxf(sqrtf(ssum), 1e-12f);
    s_q[w][lane]      = q0 * inv;
    s_q[w][lane + 32] = q1 * inv;

    long ib = (long)((b * HEADS + h) * NCTX + n) * KNN;
    s_idx[w][lane] = knn_idx[ib + lane];
    int msk = mem_mask[ib + lane];
    __syncwarp();

    const float* db = mem_db + (long)b * MDB * 128;
    const int hl = lane >> 4;
    const int sl = lane & 15;

    float4 q4 = *(const float4*)&s_q[w][sl * 4];

#pragma unroll 4
    for (int i = 0; i < 16; i++) {
        int  nb = 2 * i + hl;
        long ij = s_idx[w][nb];
        float4 k4 = *(const float4*)(db + ij * 128 + sl * 4);
        float p = fmaf(q4.x, k4.x, fmaf(q4.y, k4.y, fmaf(q4.z, k4.z, q4.w * k4.w)));
        p += __shfl_xor_sync(FULL, p, 8);
        p += __shfl_xor_sync(FULL, p, 4);
        p += __shfl_xor_sync(FULL, p, 2);
        p += __shfl_xor_sync(FULL, p, 1);
        if (sl == 0) s_sim[w][nb] = p;
    }
    __syncwarp();

    float sim = msk ? s_sim[w][lane] : -FLT_MAX;

    float m = sim;
#pragma unroll
    for (int o = 16; o > 0; o >>= 1) m = fmaxf(m, __shfl_xor_sync(FULL, m, o));
    float p = __expf(sim - m);
    float s = p;
#pragma unroll
    for (int o = 16; o > 0; o >>= 1) s += __shfl_xor_sync(FULL, s, o);
    s_att[w][lane] = p / s;
    __syncwarp();

    float4 acc = make_float4(0.f, 0.f, 0.f, 0.f);
#pragma unroll 4
    for (int i = 0; i < 16; i++) {
        int  nb = 2 * i + hl;
        long ij = s_idx[w][nb];
        float a = s_att[w][nb];
        float4 v4 = *(const float4*)(db + ij * 128 + 64 + sl * 4);
        acc.x = fmaf(a, v4.x, acc.x);
        acc.y = fmaf(a, v4.y, acc.y);
        acc.z = fmaf(a, v4.z, acc.z);
        acc.w = fmaf(a, v4.w, acc.w);
    }
    acc.x += __shfl_xor_sync(FULL, acc.x, 16);
    acc.y += __shfl_xor_sync(FULL, acc.y, 16);
    acc.z += __shfl_xor_sync(FULL, acc.z, 16);
    acc.w += __shfl_xor_sync(FULL, acc.w, 16);

    if (lane < 16) {
        float vv[4] = {acc.x, acc.y, acc.z, acc.w};
        unsigned long long hp, lp;
        split_pack4(vv, hp, lp);
        __nv_bfloat16* dst = g_a2 + (long)(b * NCTX + n) * KS + h * DHEAD + sl * 4;
        *(unsigned long long*)(dst)       = hp;
        *(unsigned long long*)(dst + 512) = lp;
    }
}

// ---------------------------------------------------------------------------
extern "C" void kernel_launch(void* const* d_in, const int* in_sizes, int n_in,
                              void* d_out, int out_size)
{
    const float* x        = (const float*)d_in[0];
    const float* mem_db   = (const float*)d_in[1];
    const int*   knn_idx  = (const int*)d_in[2];
    const int*   mem_mask = (const int*)d_in[3];
    const float* Wq       = (const float*)d_in[4];
    // d_in[5] = Wkv : dead code in the reference, never used
    const float* Wout     = (const float*)d_in[6];
    const float* scale_p  = (const float*)d_in[7];
    float* out = (float*)d_out;

    float *qb;
    __nv_bfloat16 *a2, *b2q, *b2o;
    cudaGetSymbolAddress((void**)&qb,  g_q);
    cudaGetSymbolAddress((void**)&a2,  g_a2);
    cudaGetSymbolAddress((void**)&b2q, g_b2q);
    cudaGetSymbolAddress((void**)&b2o, g_b2o);

    cudaFuncSetAttribute(gemm_mma, cudaFuncAttributeMaxDynamicSharedMemorySize, GSMEM);

    dim3 gGemm(DIM / 128, MROWS / 128);   // (4, 32) = 128 CTAs

    // 1) split x, Wq, Wout in one launch; then q = x @ Wq^T
    split_all<<<((MROWS + 2 * DIM) * (DIM / 4)) / 256, 256>>>(x, Wq, Wout);
    gemm_mma<<<gGemm, 256, GSMEM>>>(a2, b2q, qb, DIM);

    // 2) gather-attention; epilogue writes bf16 split directly into g_a2
    int nwarps = BATCH * HEADS * NCTX;            // 32768
    knn_attn5<<<nwarps / 8, 256>>>(mem_db, knn_idx, mem_mask, scale_p);

    // 3) out = attn_out @ Wout^T
    gemm_mma<<<gGemm, 256, GSMEM>>>(a2, b2o, out, DIM);
}